// round 13
// baseline (speedup 1.0000x reference)
#include <cuda_runtime.h>
#include <cuda_bf16.h>
#include <cuda_pipeline.h>
#include <cstdint>

// HSMNet cost-volume + channel-sum + softmax disparity regression, fused.
// B=4, C=32, H=80, W=160, D=24. Output [B,H,W] f32.
//
// R12: R11 + dual-parity tgt staging so the 8-float window is loaded with
// 2x LDS.128 (+1 ref LDS.64) instead of 5x LDS.64. stA = tgt[g0+l],
// stB = tgt[g0+2+l]; OFF_B-OFF_A = 64B (mod 128B) makes the A/B mix
// conflict-free (7 distinct quad-banks + 1 broadcast per 8-lane phase).
// q==0 CTAs (w_start=0) keep the R11 float2 path + halo + validity.

#define Bc 4
#define Cc 32
#define Hc 80
#define Wc 160
#define Dc 24
#define QW 40
#define NT 160
#define TROW 64
#define RROW 40
#define OFF_A 0
#define OFF_B (Cc * TROW + 16)          // 2064: 16B-aligned, +64B bank skew
#define OFF_R (OFF_B + Cc * TROW)       // 4112
#define SMEMF (OFF_R + Cc * RROW)       // 5392 floats = 21568 B

__global__ __launch_bounds__(NT, 9)
void hsm_dispreg_kernel(const float* __restrict__ ref,
                        const float* __restrict__ tgt,
                        float* __restrict__ out)
{
    __shared__ __align__(128) float sm[SMEMF];

    const int q   = blockIdx.x;              // 0..3
    const int h   = blockIdx.y;
    const int b   = blockIdx.z;
    const int tid = threadIdx.x;

    const int w_start = q * QW;
    const int rowbase = (b * Cc * Hc + h) * Wc;
    const int HW = Hc * Wc;
    const int g0 = w_start - 24;

    // ref-row copy mapping: 16 rows x 10 segs = 160 = NT
    const int rr  = tid / 10;
    const int rsg = tid - rr * 10;

    // lane mapping (identical to R9/R11)
    const int lane = tid & 31;
    const int warp = tid >> 5;               // 0..4
    const int wbq  = warp * 4 + (lane & 3);  // 0..19
    const int dg   = (lane >> 2) & 3;
    const int cg   = lane >> 4;
    const int w0   = w_start + 2 * wbq;
    const int d0   = 6 * dg;

    float c00 = 0.f, c01 = 0.f, c02 = 0.f, c03 = 0.f, c04 = 0.f, c05 = 0.f;
    float c10 = 0.f, c11 = 0.f, c12 = 0.f, c13 = 0.f, c14 = 0.f, c15 = 0.f;

    if (q == 0) {
        // ---------------- R11 path: float2 loads, halo, validity later ----
        float* st = sm + OFF_A;
        float* sr = sm + OFF_R;
#pragma unroll
        for (int k = 0; k < 5; ++k) {
            const int idx = tid + k * NT;    // 32*24 = 768 halo floats
            if (idx < Cc * 24) {
                const int c = idx / 24;
                const int l = idx - c * 24;
                st[c * TROW + l] = 0.0f;
            }
        }
#pragma unroll
        for (int g = 0; g < 2; ++g) {
            {   // tgt: valid [0,40) -> dst +24; one 16B copy per thread
                const int c = ((rr < 8) ? rr : rr + 8) + g * 8;
                __pipeline_memcpy_async(st + c * TROW + 24 + rsg * 4,
                                        tgt + rowbase + c * HW + rsg * 4, 16);
            }
            {   // ref
                const int c = ((rr < 8) ? rr : rr + 8) + g * 8;
                __pipeline_memcpy_async(sr + c * RROW + rsg * 4,
                                        ref + rowbase + c * HW + w_start + rsg * 4, 16);
            }
            __pipeline_commit();
        }

        const float* tp = st + (2 * wbq - d0 + 18);
        const float* rp = sr + 2 * wbq;

        __pipeline_wait_prior(1);
        __syncthreads();
#pragma unroll
        for (int k = 0; k < 8; ++k) {
            const int c = cg * 16 + k;
            const float2 r  = *(const float2*)(rp + c * RROW);
            const float2 tA = *(const float2*)(tp + c * TROW);
            const float2 tB = *(const float2*)(tp + c * TROW + 2);
            const float2 tC = *(const float2*)(tp + c * TROW + 4);
            const float2 tD = *(const float2*)(tp + c * TROW + 6);
            c00 += fabsf(r.x - tD.x);  c01 += fabsf(r.x - tC.y);
            c02 += fabsf(r.x - tC.x);  c03 += fabsf(r.x - tB.y);
            c04 += fabsf(r.x - tB.x);  c05 += fabsf(r.x - tA.y);
            c10 += fabsf(r.y - tD.y);  c11 += fabsf(r.y - tD.x);
            c12 += fabsf(r.y - tC.y);  c13 += fabsf(r.y - tC.x);
            c14 += fabsf(r.y - tB.y);  c15 += fabsf(r.y - tB.x);
        }
        __pipeline_wait_prior(0);
        __syncthreads();
#pragma unroll
        for (int k = 8; k < 16; ++k) {
            const int c = cg * 16 + k;
            const float2 r  = *(const float2*)(rp + c * RROW);
            const float2 tA = *(const float2*)(tp + c * TROW);
            const float2 tB = *(const float2*)(tp + c * TROW + 2);
            const float2 tC = *(const float2*)(tp + c * TROW + 4);
            const float2 tD = *(const float2*)(tp + c * TROW + 6);
            c00 += fabsf(r.x - tD.x);  c01 += fabsf(r.x - tC.y);
            c02 += fabsf(r.x - tC.x);  c03 += fabsf(r.x - tB.y);
            c04 += fabsf(r.x - tB.x);  c05 += fabsf(r.x - tA.y);
            c10 += fabsf(r.y - tD.y);  c11 += fabsf(r.y - tD.x);
            c12 += fabsf(r.y - tC.y);  c13 += fabsf(r.y - tC.x);
            c14 += fabsf(r.y - tB.y);  c15 += fabsf(r.y - tB.x);
        }
    } else {
        // ---------------- float4 path: dual-parity staging ----------------
#pragma unroll
        for (int g = 0; g < 2; ++g) {
            // stA: 16 rows x 16 segs of 16B = 256 copies
#pragma unroll
            for (int k = 0; k < 2; ++k) {
                const int idx = tid + k * NT;
                if (idx < 256) {
                    const int r8  = idx >> 4;
                    const int seg = idx & 15;
                    const int c = ((r8 < 8) ? r8 : r8 + 8) + g * 8;
                    __pipeline_memcpy_async(sm + OFF_A + c * TROW + seg * 4,
                                            tgt + rowbase + c * HW + g0 + seg * 4, 16);
                }
            }
            // stB: 16 rows x 32 segs of 8B = 512 copies (shift +2 floats)
#pragma unroll
            for (int k = 0; k < 4; ++k) {
                const int idx = tid + k * NT;
                if (idx < 512) {
                    const int r8  = idx >> 5;
                    const int seg = idx & 31;
                    const int c = ((r8 < 8) ? r8 : r8 + 8) + g * 8;
                    const int gs = g0 + 2 + seg * 2;
                    if (gs + 1 < Wc)   // guard q==3 tail (seg 31)
                        __pipeline_memcpy_async(sm + OFF_B + c * TROW + seg * 2,
                                                tgt + rowbase + c * HW + gs, 8);
                }
            }
            // ref: one 16B copy per thread
            {
                const int c = ((rr < 8) ? rr : rr + 8) + g * 8;
                __pipeline_memcpy_async(sm + OFF_R + c * RROW + rsg * 4,
                                        ref + rowbase + c * HW + w_start + rsg * 4, 16);
            }
            __pipeline_commit();
        }

        // window base u (float idx, stA space); pick array for 16B alignment
        const int u = 2 * wbq - d0 + 18;
        const float* tptr = (u & 2) ? (sm + OFF_B + (u - 2)) : (sm + OFF_A + u);
        const float* rp   = sm + OFF_R + 2 * wbq;

        __pipeline_wait_prior(1);
        __syncthreads();
#pragma unroll
        for (int k = 0; k < 8; ++k) {
            const int c = cg * 16 + k;
            const float2 r  = *(const float2*)(rp + c * RROW);
            const float4 T0 = *(const float4*)(tptr + c * TROW);      // t0..t3
            const float4 T1 = *(const float4*)(tptr + c * TROW + 4);  // t4..t7
            c00 += fabsf(r.x - T1.z);  c01 += fabsf(r.x - T1.y);
            c02 += fabsf(r.x - T1.x);  c03 += fabsf(r.x - T0.w);
            c04 += fabsf(r.x - T0.z);  c05 += fabsf(r.x - T0.y);
            c10 += fabsf(r.y - T1.w);  c11 += fabsf(r.y - T1.z);
            c12 += fabsf(r.y - T1.y);  c13 += fabsf(r.y - T1.x);
            c14 += fabsf(r.y - T0.w);  c15 += fabsf(r.y - T0.z);
        }
        __pipeline_wait_prior(0);
        __syncthreads();
#pragma unroll
        for (int k = 8; k < 16; ++k) {
            const int c = cg * 16 + k;
            const float2 r  = *(const float2*)(rp + c * RROW);
            const float4 T0 = *(const float4*)(tptr + c * TROW);
            const float4 T1 = *(const float4*)(tptr + c * TROW + 4);
            c00 += fabsf(r.x - T1.z);  c01 += fabsf(r.x - T1.y);
            c02 += fabsf(r.x - T1.x);  c03 += fabsf(r.x - T0.w);
            c04 += fabsf(r.x - T0.z);  c05 += fabsf(r.x - T0.y);
            c10 += fabsf(r.y - T1.w);  c11 += fabsf(r.y - T1.z);
            c12 += fabsf(r.y - T1.y);  c13 += fabsf(r.y - T1.x);
            c14 += fabsf(r.y - T0.w);  c15 += fabsf(r.y - T0.z);
        }
    }

    // ---- sum partial costs across cg (lanes xor 16) ----
    c00 += __shfl_xor_sync(0xffffffffu, c00, 16);
    c01 += __shfl_xor_sync(0xffffffffu, c01, 16);
    c02 += __shfl_xor_sync(0xffffffffu, c02, 16);
    c03 += __shfl_xor_sync(0xffffffffu, c03, 16);
    c04 += __shfl_xor_sync(0xffffffffu, c04, 16);
    c05 += __shfl_xor_sync(0xffffffffu, c05, 16);
    c10 += __shfl_xor_sync(0xffffffffu, c10, 16);
    c11 += __shfl_xor_sync(0xffffffffu, c11, 16);
    c12 += __shfl_xor_sync(0xffffffffu, c12, 16);
    c13 += __shfl_xor_sync(0xffffffffu, c13, 16);
    c14 += __shfl_xor_sync(0xffffffffu, c14, 16);
    c15 += __shfl_xor_sync(0xffffffffu, c15, 16);

    // validity (d > w -> cost 0): only possible in q==0
    if (q == 0) {
        if (w0 < d0    ) c00 = 0.f;
        if (w0 < d0 + 1) c01 = 0.f;
        if (w0 < d0 + 2) c02 = 0.f;
        if (w0 < d0 + 3) c03 = 0.f;
        if (w0 < d0 + 4) c04 = 0.f;
        if (w0 < d0 + 5) c05 = 0.f;
        if (w0 + 1 < d0    ) c10 = 0.f;
        if (w0 + 1 < d0 + 1) c11 = 0.f;
        if (w0 + 1 < d0 + 2) c12 = 0.f;
        if (w0 + 1 < d0 + 3) c13 = 0.f;
        if (w0 + 1 < d0 + 4) c14 = 0.f;
        if (w0 + 1 < d0 + 5) c15 = 0.f;
    }

    // ---- exact two-pass softmax + expectation across the 4 dg lanes ----
    float m0 = fmaxf(fmaxf(fmaxf(c00, c01), fmaxf(c02, c03)), fmaxf(c04, c05));
    float m1 = fmaxf(fmaxf(fmaxf(c10, c11), fmaxf(c12, c13)), fmaxf(c14, c15));
    m0 = fmaxf(m0, __shfl_xor_sync(0xffffffffu, m0, 4));
    m0 = fmaxf(m0, __shfl_xor_sync(0xffffffffu, m0, 8));
    m1 = fmaxf(m1, __shfl_xor_sync(0xffffffffu, m1, 4));
    m1 = fmaxf(m1, __shfl_xor_sync(0xffffffffu, m1, 8));

    const float e00 = __expf(c00 - m0), e01 = __expf(c01 - m0), e02 = __expf(c02 - m0);
    const float e03 = __expf(c03 - m0), e04 = __expf(c04 - m0), e05 = __expf(c05 - m0);
    const float e10 = __expf(c10 - m1), e11 = __expf(c11 - m1), e12 = __expf(c12 - m1);
    const float e13 = __expf(c13 - m1), e14 = __expf(c14 - m1), e15 = __expf(c15 - m1);

    const float fd = (float)d0;
    float s0 = ((e00 + e01) + (e02 + e03)) + (e04 + e05);
    float n0 = fd * e00 + (fd + 1.f) * e01 + (fd + 2.f) * e02
             + (fd + 3.f) * e03 + (fd + 4.f) * e04 + (fd + 5.f) * e05;
    float s1 = ((e10 + e11) + (e12 + e13)) + (e14 + e15);
    float n1 = fd * e10 + (fd + 1.f) * e11 + (fd + 2.f) * e12
             + (fd + 3.f) * e13 + (fd + 4.f) * e14 + (fd + 5.f) * e15;

    s0 += __shfl_xor_sync(0xffffffffu, s0, 4);
    s0 += __shfl_xor_sync(0xffffffffu, s0, 8);
    n0 += __shfl_xor_sync(0xffffffffu, n0, 4);
    n0 += __shfl_xor_sync(0xffffffffu, n0, 8);
    s1 += __shfl_xor_sync(0xffffffffu, s1, 4);
    s1 += __shfl_xor_sync(0xffffffffu, s1, 8);
    n1 += __shfl_xor_sync(0xffffffffu, n1, 4);
    n1 += __shfl_xor_sync(0xffffffffu, n1, 8);

    if (dg == 0 && cg == 0) {
        float2 o;
        o.x = n0 / s0;
        o.y = n1 / s1;
        *(float2*)&out[(b * Hc + h) * Wc + w0] = o;
    }
}

extern "C" void kernel_launch(void* const* d_in, const int* in_sizes, int n_in,
                              void* d_out, int out_size)
{
    const float* ref = (const float*)d_in[0];
    const float* tgt = (const float*)d_in[1];
    float* out = (float*)d_out;

    dim3 grid(4, Hc, Bc);   // 1280 CTAs x 160 threads
    hsm_dispreg_kernel<<<grid, NT>>>(ref, tgt, out);
}

// round 15
// speedup vs baseline: 1.0774x; 1.0774x over previous
#include <cuda_runtime.h>
#include <cuda_bf16.h>
#include <cuda_pipeline.h>
#include <cstdint>

// HSMNet cost-volume + channel-sum + softmax disparity regression, fused.
// B=4, C=32, H=80, W=160, D=24. Output [B,H,W] f32.
//
// R14: R13 (4-deep cp.async chunk pipeline over R11 compute) with the q==0
// staging map fixed: each chunk has 8 tgt rows + 8 ref rows; threads 0-79
// stage tgt (8 rows x 10 segs), threads 80-159 stage ref. Previously
// rr8=tid/10 in [0,15] produced channel indices up to 39 -> OOB.
// Chunk g stages channels {4g..4g+3} U {16+4g..16+4g+3}; compute consumes
// 4 channels per cg between wait_prior(3-g) points.

#define Bc 4
#define Cc 32
#define Hc 80
#define Wc 160
#define Dc 24
#define QW 40                 // pixels per CTA (quarter row)
#define NT 160
#define TROW 64               // tgt cols staged: [w_start-24, w_start+40)
#define RROW 40               // ref cols staged: [w_start, w_start+40)

__global__ __launch_bounds__(NT, 9)
void hsm_dispreg_kernel(const float* __restrict__ ref,
                        const float* __restrict__ tgt,
                        float* __restrict__ out)
{
    __shared__ __align__(16) float st[Cc * TROW];   // 2048 floats
    __shared__ __align__(16) float sr[Cc * RROW];   // 1280 floats

    const int q   = blockIdx.x;              // 0..3
    const int h   = blockIdx.y;
    const int b   = blockIdx.z;
    const int tid = threadIdx.x;

    const int w_start = q * QW;
    const int rowbase = (b * Cc * Hc + h) * Wc;
    const int HW = Hc * Wc;
    const int g0 = w_start - 24;

    // q==0: zero the 24-float left halo of every tgt row (synchronous STS).
    if (q == 0) {
#pragma unroll
        for (int k = 0; k < 5; ++k) {
            const int idx = tid + k * NT;    // covers 32*24 = 768
            if (idx < Cc * 24) {
                const int c = idx / 24;
                const int l = idx - c * 24;
                st[c * TROW + l] = 0.0f;
            }
        }
    }

    // ---- issue 4 chunks of async copies, one commit per chunk ----
    // chunk g: channels {4g..4g+3} U {16+4g..16+4g+3}  (8 rows)
    if (q == 0) {
        // per chunk: tgt 8 rows x 10 segs = 80 copies (threads 0-79),
        //            ref 8 rows x 10 segs = 80 copies (threads 80-159)
#pragma unroll
        for (int g = 0; g < 4; ++g) {
            if (tid < 80) {
                const int r8 = tid / 10;             // 0..7
                const int sg = tid - r8 * 10;        // 0..9
                const int c  = ((r8 < 4) ? r8 : r8 + 12) + g * 4;
                __pipeline_memcpy_async(st + c * TROW + 24 + sg * 4,
                                        tgt + rowbase + c * HW + sg * 4, 16);
            } else {
                const int j  = tid - 80;
                const int r8 = j / 10;               // 0..7
                const int sg = j - r8 * 10;          // 0..9
                const int c  = ((r8 < 4) ? r8 : r8 + 12) + g * 4;
                __pipeline_memcpy_async(sr + c * RROW + sg * 4,
                                        ref + rowbase + c * HW + w_start + sg * 4, 16);
            }
            __pipeline_commit();
        }
    } else {
#pragma unroll
        for (int g = 0; g < 4; ++g) {
            // tgt: 8 rows x 16 segs = 128 copies; ref: 8 rows x 10 = 80
            // 208 copies enumerated with idx = tid, tid+160
#pragma unroll
            for (int k = 0; k < 2; ++k) {
                const int idx = tid + k * NT;
                if (idx < 128) {
                    const int r8  = idx >> 4;             // 0..7
                    const int seg = idx & 15;
                    const int c = ((r8 < 4) ? r8 : r8 + 12) + g * 4;
                    __pipeline_memcpy_async(st + c * TROW + seg * 4,
                                            tgt + rowbase + c * HW + g0 + seg * 4, 16);
                } else if (idx < 208) {
                    const int j   = idx - 128;
                    const int r8  = j / 10;               // 0..7
                    const int seg = j - r8 * 10;          // 0..9
                    const int c = ((r8 < 4) ? r8 : r8 + 12) + g * 4;
                    __pipeline_memcpy_async(sr + c * RROW + seg * 4,
                                            ref + rowbase + c * HW + w_start + seg * 4, 16);
                }
            }
            __pipeline_commit();
        }
    }

    // ---- lane mapping (identical to R9/R11) ----
    const int lane = tid & 31;
    const int warp = tid >> 5;               // 0..4
    const int wbq  = warp * 4 + (lane & 3);  // 0..19
    const int dg   = (lane >> 2) & 3;
    const int cg   = lane >> 4;
    const int w0   = w_start + 2 * wbq;
    const int d0   = 6 * dg;

    const float* tp = st + (2 * wbq - d0 + 18);        // + c*TROW
    const float* rp = sr + 2 * wbq;                    // + c*RROW

    float c00 = 0.f, c01 = 0.f, c02 = 0.f, c03 = 0.f, c04 = 0.f, c05 = 0.f;
    float c10 = 0.f, c11 = 0.f, c12 = 0.f, c13 = 0.f, c14 = 0.f, c15 = 0.f;

    // ---- 4-stage consume: wait_prior(3-g), sync, compute 4 channels/cg ----
#pragma unroll
    for (int g = 0; g < 4; ++g) {
        if (g == 0) __pipeline_wait_prior(3);
        else if (g == 1) __pipeline_wait_prior(2);
        else if (g == 2) __pipeline_wait_prior(1);
        else __pipeline_wait_prior(0);
        __syncthreads();

#pragma unroll
        for (int k = 0; k < 4; ++k) {
            const int c = cg * 16 + g * 4 + k;
            const float2 r  = *(const float2*)(rp + c * RROW);
            const float2 tA = *(const float2*)(tp + c * TROW);
            const float2 tB = *(const float2*)(tp + c * TROW + 2);
            const float2 tC = *(const float2*)(tp + c * TROW + 4);
            const float2 tD = *(const float2*)(tp + c * TROW + 6);
            c00 += fabsf(r.x - tD.x);
            c01 += fabsf(r.x - tC.y);
            c02 += fabsf(r.x - tC.x);
            c03 += fabsf(r.x - tB.y);
            c04 += fabsf(r.x - tB.x);
            c05 += fabsf(r.x - tA.y);
            c10 += fabsf(r.y - tD.y);
            c11 += fabsf(r.y - tD.x);
            c12 += fabsf(r.y - tC.y);
            c13 += fabsf(r.y - tC.x);
            c14 += fabsf(r.y - tB.y);
            c15 += fabsf(r.y - tB.x);
        }
    }

    // ---- sum partial costs across cg (lanes xor 16) ----
    c00 += __shfl_xor_sync(0xffffffffu, c00, 16);
    c01 += __shfl_xor_sync(0xffffffffu, c01, 16);
    c02 += __shfl_xor_sync(0xffffffffu, c02, 16);
    c03 += __shfl_xor_sync(0xffffffffu, c03, 16);
    c04 += __shfl_xor_sync(0xffffffffu, c04, 16);
    c05 += __shfl_xor_sync(0xffffffffu, c05, 16);
    c10 += __shfl_xor_sync(0xffffffffu, c10, 16);
    c11 += __shfl_xor_sync(0xffffffffu, c11, 16);
    c12 += __shfl_xor_sync(0xffffffffu, c12, 16);
    c13 += __shfl_xor_sync(0xffffffffu, c13, 16);
    c14 += __shfl_xor_sync(0xffffffffu, c14, 16);
    c15 += __shfl_xor_sync(0xffffffffu, c15, 16);

    // validity (d > w -> cost 0): only possible in q==0 CTAs (w0 <= 38)
    if (q == 0) {
        if (w0 < d0    ) c00 = 0.f;
        if (w0 < d0 + 1) c01 = 0.f;
        if (w0 < d0 + 2) c02 = 0.f;
        if (w0 < d0 + 3) c03 = 0.f;
        if (w0 < d0 + 4) c04 = 0.f;
        if (w0 < d0 + 5) c05 = 0.f;
        if (w0 + 1 < d0    ) c10 = 0.f;
        if (w0 + 1 < d0 + 1) c11 = 0.f;
        if (w0 + 1 < d0 + 2) c12 = 0.f;
        if (w0 + 1 < d0 + 3) c13 = 0.f;
        if (w0 + 1 < d0 + 4) c14 = 0.f;
        if (w0 + 1 < d0 + 5) c15 = 0.f;
    }

    // ---- exact two-pass softmax + expectation across the 4 dg lanes ----
    float m0 = fmaxf(fmaxf(fmaxf(c00, c01), fmaxf(c02, c03)), fmaxf(c04, c05));
    float m1 = fmaxf(fmaxf(fmaxf(c10, c11), fmaxf(c12, c13)), fmaxf(c14, c15));
    m0 = fmaxf(m0, __shfl_xor_sync(0xffffffffu, m0, 4));
    m0 = fmaxf(m0, __shfl_xor_sync(0xffffffffu, m0, 8));
    m1 = fmaxf(m1, __shfl_xor_sync(0xffffffffu, m1, 4));
    m1 = fmaxf(m1, __shfl_xor_sync(0xffffffffu, m1, 8));

    const float e00 = __expf(c00 - m0), e01 = __expf(c01 - m0), e02 = __expf(c02 - m0);
    const float e03 = __expf(c03 - m0), e04 = __expf(c04 - m0), e05 = __expf(c05 - m0);
    const float e10 = __expf(c10 - m1), e11 = __expf(c11 - m1), e12 = __expf(c12 - m1);
    const float e13 = __expf(c13 - m1), e14 = __expf(c14 - m1), e15 = __expf(c15 - m1);

    const float fd = (float)d0;
    float s0 = ((e00 + e01) + (e02 + e03)) + (e04 + e05);
    float n0 = fd * e00 + (fd + 1.f) * e01 + (fd + 2.f) * e02
             + (fd + 3.f) * e03 + (fd + 4.f) * e04 + (fd + 5.f) * e05;
    float s1 = ((e10 + e11) + (e12 + e13)) + (e14 + e15);
    float n1 = fd * e10 + (fd + 1.f) * e11 + (fd + 2.f) * e12
             + (fd + 3.f) * e13 + (fd + 4.f) * e14 + (fd + 5.f) * e15;

    s0 += __shfl_xor_sync(0xffffffffu, s0, 4);
    s0 += __shfl_xor_sync(0xffffffffu, s0, 8);
    n0 += __shfl_xor_sync(0xffffffffu, n0, 4);
    n0 += __shfl_xor_sync(0xffffffffu, n0, 8);
    s1 += __shfl_xor_sync(0xffffffffu, s1, 4);
    s1 += __shfl_xor_sync(0xffffffffu, s1, 8);
    n1 += __shfl_xor_sync(0xffffffffu, n1, 4);
    n1 += __shfl_xor_sync(0xffffffffu, n1, 8);

    if (dg == 0 && cg == 0) {
        float2 o;
        o.x = n0 / s0;
        o.y = n1 / s1;
        *(float2*)&out[(b * Hc + h) * Wc + w0] = o;
    }
}

extern "C" void kernel_launch(void* const* d_in, const int* in_sizes, int n_in,
                              void* d_out, int out_size)
{
    const float* ref = (const float*)d_in[0];
    const float* tgt = (const float*)d_in[1];
    float* out = (float*)d_out;

    dim3 grid(4, Hc, Bc);   // 1280 CTAs x 160 threads
    hsm_dispreg_kernel<<<grid, NT>>>(ref, tgt, out);
}